// round 5
// baseline (speedup 1.0000x reference)
#include <cuda_runtime.h>
#include <cstdint>
#include <cstddef>

#define NP 200000
#define NA 100000
#define EC 4000000
#define EW 2000000

// ---------------- device scratch (allocation-free) ----------------
__device__ float g_xls[(size_t)NP * 64];   // dis-scaled x_paper @ gcn_W
__device__ float g_P  [(size_t)NP * 64];   // paper accumulation
__device__ float g_SA [(size_t)NP * 64];   // sage neighbor mean
__device__ float g_XS [(size_t)NP * 64];   // gat source feats (paper)
__device__ float g_XD [(size_t)NA * 64];   // gat dst feats (author)
__device__ float g_xp1[(size_t)NP * 64];   // x_paper after layer 0
__device__ float g_xa1[(size_t)NA * 64];   // x_author after layer 0/1
__device__ float g_dis [NP];
__device__ float g_asrc[NP];
__device__ float g_adst[NA];
__device__ int g_degC[NP], g_degWp[NP], g_degWa[NA];
__device__ int g_offC[NP], g_offWp[NP], g_offWa[NA];
__device__ int g_curC[NP], g_curWp[NP], g_curWa[NA];
__device__ int g_bsum[512];
__device__ int g_csrC[EC], g_csrWp[EW], g_csrWa[EW];

// ---------------- utility kernels ----------------
__global__ void k_count(const int* __restrict__ idx, int* cnt, int E) {
    int i = blockIdx.x * blockDim.x + threadIdx.x;
    if (i < E) atomicAdd(&cnt[idx[i]], 1);
}
__global__ void k_dis(const int* __restrict__ cnt, float* dis, int n) {
    int i = blockIdx.x * blockDim.x + threadIdx.x;
    if (i < n) dis[i] = rsqrtf((float)cnt[i] + 1.0f);
}

// ---------------- scan (3-phase, blocks of 512) ----------------
__global__ void k_scan1(const int* __restrict__ deg, int* off, int* bsum, int n) {
    __shared__ int sh[512];
    int t = threadIdx.x, i = blockIdx.x * 512 + t;
    int v = (i < n) ? deg[i] : 0;
    sh[t] = v; __syncthreads();
    #pragma unroll
    for (int o = 1; o < 512; o <<= 1) {
        int x = (t >= o) ? sh[t - o] : 0;
        __syncthreads(); sh[t] += x; __syncthreads();
    }
    if (i < n) off[i] = sh[t] - v;
    if (t == 511) bsum[blockIdx.x] = sh[511];
}
__global__ void k_scan2(int* bsum, int nb) {
    __shared__ int sh[512];
    int t = threadIdx.x;
    int v = (t < nb) ? bsum[t] : 0;
    sh[t] = v; __syncthreads();
    #pragma unroll
    for (int o = 1; o < 512; o <<= 1) {
        int x = (t >= o) ? sh[t - o] : 0;
        __syncthreads(); sh[t] += x; __syncthreads();
    }
    if (t < nb) bsum[t] = sh[t] - v;
}
__global__ void k_scan3(int* off, int* cur, const int* __restrict__ bsum, int n) {
    int i = blockIdx.x * blockDim.x + threadIdx.x;
    if (i < n) { int v = off[i] + bsum[i >> 9]; off[i] = v; cur[i] = v; }
}
__global__ void k_fill(const int* __restrict__ dst, const int* __restrict__ src,
                       int* cur, int* csr, int E) {
    int i = blockIdx.x * blockDim.x + threadIdx.x;
    if (i < E) {
        int pos = atomicAdd(&cur[dst[i]], 1);
        csr[pos] = src[i];
    }
}

// ---------------- gathers (1 warp / node, 2 cols / lane) ----------------
// P += dis[w] * (sum_{nbr} xls[nbr] + xls[w])   (P pre-holds sage_Wr part)
__global__ void k_gcn_gather(const int* __restrict__ off, const int* __restrict__ csr,
                             const float* __restrict__ xls, const float* __restrict__ dis,
                             float* __restrict__ P, int n, int E) {
    int w = (blockIdx.x * blockDim.x + threadIdx.x) >> 5;
    int lane = threadIdx.x & 31;
    if (w >= n) return;
    int beg = off[w], end = (w == n - 1) ? E : off[w + 1];
    float a0 = 0.f, a1 = 0.f;
    int t = beg;
    for (; t + 4 <= end; t += 4) {
        int s0 = __ldg(&csr[t]),     s1 = __ldg(&csr[t + 1]);
        int s2 = __ldg(&csr[t + 2]), s3 = __ldg(&csr[t + 3]);
        float b0 = xls[s0 * 64 + lane],      c0 = xls[s0 * 64 + 32 + lane];
        float b1 = xls[s1 * 64 + lane],      c1 = xls[s1 * 64 + 32 + lane];
        float b2 = xls[s2 * 64 + lane],      c2 = xls[s2 * 64 + 32 + lane];
        float b3 = xls[s3 * 64 + lane],      c3 = xls[s3 * 64 + 32 + lane];
        a0 += (b0 + b1) + (b2 + b3);
        a1 += (c0 + c1) + (c2 + c3);
    }
    for (; t < end; t++) {
        int s = __ldg(&csr[t]);
        a0 += xls[s * 64 + lane];
        a1 += xls[s * 64 + 32 + lane];
    }
    float dd = dis[w];
    P[(size_t)w * 64 + lane]      += dd * (a0 + xls[w * 64 + lane]);
    P[(size_t)w * 64 + 32 + lane] += dd * (a1 + xls[w * 64 + 32 + lane]);
}

__global__ void k_sage_gather(const int* __restrict__ off, const int* __restrict__ csr,
                              const float* __restrict__ xa, float* __restrict__ SA,
                              int n, int E) {
    int w = (blockIdx.x * blockDim.x + threadIdx.x) >> 5;
    int lane = threadIdx.x & 31;
    if (w >= n) return;
    int beg = off[w], end = (w == n - 1) ? E : off[w + 1];
    float a0 = 0.f, a1 = 0.f;
    int t = beg;
    for (; t + 4 <= end; t += 4) {
        int s0 = __ldg(&csr[t]),     s1 = __ldg(&csr[t + 1]);
        int s2 = __ldg(&csr[t + 2]), s3 = __ldg(&csr[t + 3]);
        float b0 = xa[s0 * 64 + lane],      c0 = xa[s0 * 64 + 32 + lane];
        float b1 = xa[s1 * 64 + lane],      c1 = xa[s1 * 64 + 32 + lane];
        float b2 = xa[s2 * 64 + lane],      c2 = xa[s2 * 64 + 32 + lane];
        float b3 = xa[s3 * 64 + lane],      c3 = xa[s3 * 64 + 32 + lane];
        a0 += (b0 + b1) + (b2 + b3);
        a1 += (c0 + c1) + (c2 + c3);
    }
    for (; t < end; t++) {
        int s = __ldg(&csr[t]);
        a0 += xa[s * 64 + lane];
        a1 += xa[s * 64 + 32 + lane];
    }
    float r = 1.0f / fmaxf((float)(end - beg), 1.0f);
    SA[(size_t)w * 64 + lane]      = a0 * r;
    SA[(size_t)w * 64 + 32 + lane] = a1 * r;
}

// fused GAT: per-author softmax denom + weighted gather + bias + relu
__global__ void k_gat_gather(const int* __restrict__ off, const int* __restrict__ csr,
                             const float* __restrict__ asrc, const float* __restrict__ adst,
                             const float* __restrict__ XS, const float* __restrict__ bias,
                             float* __restrict__ out, int n, int E) {
    int w = (blockIdx.x * blockDim.x + threadIdx.x) >> 5;
    int lane = threadIdx.x & 31;
    if (w >= n) return;
    int beg = off[w], end = (w == n - 1) ? E : off[w + 1];
    float ad = adst[w];
    float den = 0.f, a0 = 0.f, a1 = 0.f;
    int t = beg;
    for (; t + 4 <= end; t += 4) {
        int p0 = __ldg(&csr[t]),     p1 = __ldg(&csr[t + 1]);
        int p2 = __ldg(&csr[t + 2]), p3 = __ldg(&csr[t + 3]);
        float e0 = asrc[p0] + ad; e0 = (e0 > 0.f) ? e0 : 0.2f * e0;
        float e1 = asrc[p1] + ad; e1 = (e1 > 0.f) ? e1 : 0.2f * e1;
        float e2 = asrc[p2] + ad; e2 = (e2 > 0.f) ? e2 : 0.2f * e2;
        float e3 = asrc[p3] + ad; e3 = (e3 > 0.f) ? e3 : 0.2f * e3;
        float x0 = __expf(e0), x1 = __expf(e1), x2 = __expf(e2), x3 = __expf(e3);
        float b0 = XS[p0 * 64 + lane],      c0 = XS[p0 * 64 + 32 + lane];
        float b1 = XS[p1 * 64 + lane],      c1 = XS[p1 * 64 + 32 + lane];
        float b2 = XS[p2 * 64 + lane],      c2 = XS[p2 * 64 + 32 + lane];
        float b3 = XS[p3 * 64 + lane],      c3 = XS[p3 * 64 + 32 + lane];
        den += (x0 + x1) + (x2 + x3);
        a0 += (x0 * b0 + x1 * b1) + (x2 * b2 + x3 * b3);
        a1 += (x0 * c0 + x1 * c1) + (x2 * c2 + x3 * c3);
    }
    for (; t < end; t++) {
        int p = __ldg(&csr[t]);
        float e = asrc[p] + ad; e = (e > 0.f) ? e : 0.2f * e;
        float x = __expf(e);
        den += x;
        a0 += x * XS[p * 64 + lane];
        a1 += x * XS[p * 64 + 32 + lane];
    }
    float r = (den > 0.f) ? (1.0f / den) : 0.f;
    float o0 = a0 * r + bias[lane];
    float o1 = a1 * r + bias[lane + 32];
    out[(size_t)w * 64 + lane]      = fmaxf(o0, 0.f);
    out[(size_t)w * 64 + 32 + lane] = fmaxf(o1, 0.f);
}

// ---------------- f32x2 register-blocked GEMM (round-3 proven mainloop) ----------------
// Y[M,N] = X[M,K] @ W[K,N]. 256 thr, tile M=128, thread = 4 rows x (N/8) cols.
// Epilogue options (all optional, nullptr = skip):
//   rowscale: Y *= rowscale[row]
//   bias:     Y += bias[col]
//   mode 2:   Y = relu(acc + addsrc[row,col] + bias + bias2)
//   av/dotout: dotout[row] = dot(final Y row, av) via 8-lane shuffle reduce
template <int K, int N>
__global__ void __launch_bounds__(256) k_gemm2(
        const float* __restrict__ X, const float* __restrict__ W,
        const float* __restrict__ bias, const float* __restrict__ bias2,
        const float* __restrict__ addsrc, const float* __restrict__ rowscale,
        const float* __restrict__ av, float* __restrict__ dotout,
        float* __restrict__ Y, int M, int mode) {
    constexpr int CPT = N / 8;
    constexpr int QP  = CPT / 2;
    __shared__ __align__(16) float  Wc[32 * N];
    __shared__ __align__(16) float2 Xd[128 * 33];
    int tid = threadIdx.x;
    int tx = tid & 7, ty = tid >> 3;
    int base = blockIdx.x * 128;

    unsigned long long accv[4][QP];
    #pragma unroll
    for (int i = 0; i < 4; i++)
        #pragma unroll
        for (int q = 0; q < QP; q++) accv[i][q] = 0ull;

    for (int kc = 0; kc < K; kc += 32) {
        __syncthreads();
        #pragma unroll
        for (int it = 0; it < (32 * N) / 256; it++) {
            int t = tid + it * 256;
            Wc[t] = W[kc * N + t];
        }
        #pragma unroll
        for (int it = 0; it < 16; it++) {
            int idx = tid + it * 256;
            int r = idx >> 5, k = idx & 31;
            int rr = base + r;
            float v = (rr < M) ? X[(size_t)rr * K + kc + k] : 0.f;
            Xd[r * 33 + k] = make_float2(v, v);
        }
        __syncthreads();
        #pragma unroll
        for (int k = 0; k < 32; k++) {
            unsigned long long a[4];
            #pragma unroll
            for (int i = 0; i < 4; i++)
                a[i] = *(const unsigned long long*)&Xd[(ty * 4 + i) * 33 + k];
            #pragma unroll
            for (int h = 0; h < QP / 2; h++) {
                ulonglong2 wp = *(const ulonglong2*)&Wc[k * N + tx * CPT + h * 4];
                #pragma unroll
                for (int i = 0; i < 4; i++) {
                    asm("fma.rn.f32x2 %0, %1, %2, %0;"
                        : "+l"(accv[i][2 * h]) : "l"(a[i]), "l"(wp.x));
                    asm("fma.rn.f32x2 %0, %1, %2, %0;"
                        : "+l"(accv[i][2 * h + 1]) : "l"(a[i]), "l"(wp.y));
                }
            }
        }
    }
    #pragma unroll
    for (int i = 0; i < 4; i++) {
        int row = base + ty * 4 + i;
        bool ok = (row < M);
        float d = 0.f;
        float rs = (ok && rowscale) ? rowscale[row] : 1.f;
        #pragma unroll
        for (int q = 0; q < QP; q++) {
            float2 v = *(float2*)&accv[i][q];
            int col = tx * CPT + 2 * q;
            if (ok) {
                if (mode == 2) {
                    float2 a2 = *(const float2*)&addsrc[(size_t)row * N + col];
                    float2 b  = *(const float2*)&bias[col];
                    float2 b2 = *(const float2*)&bias2[col];
                    v.x = fmaxf(v.x + a2.x + b.x + b2.x, 0.f);
                    v.y = fmaxf(v.y + a2.y + b.y + b2.y, 0.f);
                } else {
                    if (bias) { v.x += bias[col]; v.y += bias[col + 1]; }
                    v.x *= rs; v.y *= rs;
                }
                *(float2*)&Y[(size_t)row * N + col] = v;
                if (av) {
                    float2 w2 = *(const float2*)&av[col];
                    d += v.x * w2.x + v.y * w2.y;
                }
            }
        }
        if (av) {
            #pragma unroll
            for (int o = 1; o < 8; o <<= 1) d += __shfl_xor_sync(0xFFFFFFFFu, d, o);
            if (tx == 0 && ok) dotout[row] = d;
        }
    }
}

// ---------------- host ----------------
static inline int cdiv(long long a, int b) { return (int)((a + b - 1) / b); }

extern "C" void kernel_launch(void* const* d_in, const int* in_sizes, int n_in,
                              void* d_out, int out_size) {
    const float* xp       = (const float*)d_in[0];
    const float* xa       = (const float*)d_in[1];
    const float* gcn_W0   = (const float*)d_in[2];
    const float* gcn_b0   = (const float*)d_in[3];
    const float* sage_Wl0 = (const float*)d_in[4];
    const float* sage_bl0 = (const float*)d_in[5];
    const float* sage_Wr0 = (const float*)d_in[6];
    const float* gat_Ws0  = (const float*)d_in[7];
    const float* gat_Wd0  = (const float*)d_in[8];
    const float* gat_as0  = (const float*)d_in[9];
    const float* gat_ad0  = (const float*)d_in[10];
    const float* gat_b0   = (const float*)d_in[11];
    const float* gat_Ws1  = (const float*)d_in[17];
    const float* gat_Wd1  = (const float*)d_in[18];
    const float* gat_as1  = (const float*)d_in[19];
    const float* gat_ad1  = (const float*)d_in[20];
    const float* gat_b1   = (const float*)d_in[21];
    const float* lin_W    = (const float*)d_in[22];
    const float* lin_b    = (const float*)d_in[23];
    const int* cs = (const int*)d_in[24];
    const int* cd = (const int*)d_in[25];
    const int* ws = (const int*)d_in[26];  // author idx of writes edge
    const int* wd = (const int*)d_in[27];  // paper idx of writes edge
    float* out = (float*)d_out;

    void* p;
    #define SYM(name) cudaGetSymbolAddress(&p, g_##name)
    SYM(xls);  float* xls = (float*)p;
    SYM(P);    float* P   = (float*)p;
    SYM(SA);   float* SA  = (float*)p;
    SYM(XS);   float* XS  = (float*)p;
    SYM(XD);   float* XD  = (float*)p;
    SYM(xp1);  float* xp1 = (float*)p;
    SYM(xa1);  float* xa1 = (float*)p;
    SYM(dis);  float* dis = (float*)p;
    SYM(asrc); float* asrc = (float*)p;
    SYM(adst); float* adst = (float*)p;
    SYM(degC); int* degC = (int*)p;
    SYM(degWp); int* degWp = (int*)p;
    SYM(degWa); int* degWa = (int*)p;
    SYM(offC); int* offC = (int*)p;
    SYM(offWp); int* offWp = (int*)p;
    SYM(offWa); int* offWa = (int*)p;
    SYM(curC); int* curC = (int*)p;
    SYM(curWp); int* curWp = (int*)p;
    SYM(curWa); int* curWa = (int*)p;
    SYM(bsum); int* bsum = (int*)p;
    SYM(csrC); int* csrC = (int*)p;
    SYM(csrWp); int* csrWp = (int*)p;
    SYM(csrWa); int* csrWa = (int*)p;
    #undef SYM

    const int T = 256;

    // ---- CSR build: cites-by-dst(paper), writes-by-paper, writes-by-author ----
    cudaMemsetAsync(degC, 0, NP * sizeof(int));
    cudaMemsetAsync(degWp, 0, NP * sizeof(int));
    cudaMemsetAsync(degWa, 0, NA * sizeof(int));
    k_count<<<cdiv(EC, T), T>>>(cd, degC, EC);
    k_count<<<cdiv(EW, T), T>>>(wd, degWp, EW);
    k_count<<<cdiv(EW, T), T>>>(ws, degWa, EW);
    k_dis<<<cdiv(NP, T), T>>>(degC, dis, NP);

    k_scan1<<<cdiv(NP, 512), 512>>>(degC, offC, bsum, NP);
    k_scan2<<<1, 512>>>(bsum, cdiv(NP, 512));
    k_scan3<<<cdiv(NP, T), T>>>(offC, curC, bsum, NP);
    k_fill<<<cdiv(EC, T), T>>>(cd, cs, curC, csrC, EC);

    k_scan1<<<cdiv(NP, 512), 512>>>(degWp, offWp, bsum, NP);
    k_scan2<<<1, 512>>>(bsum, cdiv(NP, 512));
    k_scan3<<<cdiv(NP, T), T>>>(offWp, curWp, bsum, NP);
    k_fill<<<cdiv(EW, T), T>>>(wd, ws, curWp, csrWp, EW);

    k_scan1<<<cdiv(NA, 512), 512>>>(degWa, offWa, bsum, NA);
    k_scan2<<<1, 512>>>(bsum, cdiv(NA, 512));
    k_scan3<<<cdiv(NA, T), T>>>(offWa, curWa, bsum, NA);
    k_fill<<<cdiv(EW, T), T>>>(ws, wd, curWa, csrWa, EW);

    // ---- layer 0: GCN (paper<-paper) + SAGE root term ----
    k_gemm2<128, 64><<<cdiv(NP, 128), 256>>>(xp, gcn_W0, nullptr, nullptr, nullptr,
                                             dis, nullptr, nullptr, xls, NP, 0);
    k_gemm2<128, 64><<<cdiv(NP, 128), 256>>>(xp, sage_Wr0, nullptr, nullptr, nullptr,
                                             nullptr, nullptr, nullptr, P, NP, 0);
    k_gcn_gather<<<cdiv((long long)NP * 32, T), T>>>(offC, csrC, xls, dis, P, NP, EC);

    // ---- layer 0: SAGE gather + fused combine (relu(P + SA@Wl + b0 + b1)) ----
    k_sage_gather<<<cdiv((long long)NP * 32, T), T>>>(offWp, csrWp, xa, SA, NP, EW);
    k_gemm2<64, 64><<<cdiv(NP, 128), 256>>>(SA, sage_Wl0, gcn_b0, sage_bl0, P,
                                            nullptr, nullptr, nullptr, xp1, NP, 2);

    // ---- layer 0: GAT (author<-paper), rowdots fused into GEMM epilogues ----
    k_gemm2<128, 64><<<cdiv(NP, 128), 256>>>(xp, gat_Ws0, nullptr, nullptr, nullptr,
                                             nullptr, gat_as0, asrc, XS, NP, 0);
    k_gemm2<64, 64><<<cdiv(NA, 128), 256>>>(xa, gat_Wd0, nullptr, nullptr, nullptr,
                                            nullptr, gat_ad0, adst, XD, NA, 0);
    k_gat_gather<<<cdiv((long long)NA * 32, T), T>>>(offWa, csrWa, asrc, adst, XS,
                                                     gat_b0, xa1, NA, EW);

    // ---- layer 1: only GAT is live (paper update is dead code) ----
    k_gemm2<64, 64><<<cdiv(NP, 128), 256>>>(xp1, gat_Ws1, nullptr, nullptr, nullptr,
                                            nullptr, gat_as1, asrc, XS, NP, 0);
    k_gemm2<64, 64><<<cdiv(NA, 128), 256>>>(xa1, gat_Wd1, nullptr, nullptr, nullptr,
                                            nullptr, gat_ad1, adst, XD, NA, 0);
    k_gat_gather<<<cdiv((long long)NA * 32, T), T>>>(offWa, csrWa, asrc, adst, XS,
                                                     gat_b1, xa1, NA, EW);

    // ---- output head ----
    k_gemm2<64, 32><<<cdiv(NA, 128), 256>>>(xa1, lin_W, lin_b, nullptr, nullptr,
                                            nullptr, nullptr, nullptr, out, NA, 0);
}

// round 6
// speedup vs baseline: 1.0712x; 1.0712x over previous
#include <cuda_runtime.h>
#include <cstdint>
#include <cstddef>

#define NP 200000
#define NA 100000
#define EC 4000000
#define EW 2000000

// ---------------- device scratch (allocation-free) ----------------
__device__ float g_xls[(size_t)NP * 64];   // dis-scaled x_paper @ gcn_W
__device__ float g_P  [(size_t)NP * 64];   // paper accumulation
__device__ float g_SA [(size_t)NP * 64];   // sage neighbor mean
__device__ float g_XS [(size_t)NP * 64];   // gat source feats (paper)
__device__ float g_XD [(size_t)NA * 64];   // gat dst feats (author)
__device__ float g_xp1[(size_t)NP * 64];   // x_paper after layer 0
__device__ float g_xa1[(size_t)NA * 64];   // x_author after layer 0/1
__device__ float g_dis [NP];
__device__ float g_asrc[NP];
__device__ float g_adst[NA];
__device__ int g_degC[NP], g_degWp[NP], g_degWa[NA];
__device__ int g_offC[NP], g_offWp[NP], g_offWa[NA];
__device__ int g_curC[NP], g_curWp[NP], g_curWa[NA];
__device__ int g_bsum[512];
__device__ int g_csrC[EC], g_csrWp[EW], g_csrWa[EW];

// ---------------- utility kernels ----------------
__global__ void k_zero_i(int* p, int n) {
    int i = blockIdx.x * blockDim.x + threadIdx.x;
    if (i < n) p[i] = 0;
}
__global__ void k_count(const int* __restrict__ idx, int* cnt, int E) {
    int i = blockIdx.x * blockDim.x + threadIdx.x;
    if (i < E) atomicAdd(&cnt[idx[i]], 1);
}
__global__ void k_dis(const int* __restrict__ cnt, float* dis, int n) {
    int i = blockIdx.x * blockDim.x + threadIdx.x;
    if (i < n) dis[i] = rsqrtf((float)cnt[i] + 1.0f);
}

// ---------------- scan (3-phase, blocks of 512) ----------------
__global__ void k_scan1(const int* __restrict__ deg, int* off, int* bsum, int n) {
    __shared__ int sh[512];
    int t = threadIdx.x, i = blockIdx.x * 512 + t;
    int v = (i < n) ? deg[i] : 0;
    sh[t] = v; __syncthreads();
    #pragma unroll
    for (int o = 1; o < 512; o <<= 1) {
        int x = (t >= o) ? sh[t - o] : 0;
        __syncthreads(); sh[t] += x; __syncthreads();
    }
    if (i < n) off[i] = sh[t] - v;
    if (t == 511) bsum[blockIdx.x] = sh[511];
}
__global__ void k_scan2(int* bsum, int nb) {
    __shared__ int sh[512];
    int t = threadIdx.x;
    int v = (t < nb) ? bsum[t] : 0;
    sh[t] = v; __syncthreads();
    #pragma unroll
    for (int o = 1; o < 512; o <<= 1) {
        int x = (t >= o) ? sh[t - o] : 0;
        __syncthreads(); sh[t] += x; __syncthreads();
    }
    if (t < nb) bsum[t] = sh[t] - v;
}
__global__ void k_scan3(int* off, int* cur, const int* __restrict__ bsum, int n) {
    int i = blockIdx.x * blockDim.x + threadIdx.x;
    if (i < n) { int v = off[i] + bsum[i >> 9]; off[i] = v; cur[i] = v; }
}
__global__ void k_fill(const int* __restrict__ dst, const int* __restrict__ src,
                       int* cur, int* csr, int E) {
    int i = blockIdx.x * blockDim.x + threadIdx.x;
    if (i < E) {
        int pos = atomicAdd(&cur[dst[i]], 1);
        csr[pos] = src[i];
    }
}

// ---------------- gathers (1 warp / node, 2 cols / lane) ----------------
// P += dis[w] * (sum_{nbr} xls[nbr] + xls[w])   (P pre-holds sage_Wr part)
__global__ void k_gcn_gather(const int* __restrict__ off, const int* __restrict__ csr,
                             const float* __restrict__ xls, const float* __restrict__ dis,
                             float* __restrict__ P, int n, int E) {
    int w = (blockIdx.x * blockDim.x + threadIdx.x) >> 5;
    int lane = threadIdx.x & 31;
    if (w >= n) return;
    int beg = off[w], end = (w == n - 1) ? E : off[w + 1];
    float a0 = 0.f, a1 = 0.f;
    int t = beg;
    for (; t + 4 <= end; t += 4) {
        int s0 = __ldg(&csr[t]),     s1 = __ldg(&csr[t + 1]);
        int s2 = __ldg(&csr[t + 2]), s3 = __ldg(&csr[t + 3]);
        float b0 = xls[s0 * 64 + lane],      c0 = xls[s0 * 64 + 32 + lane];
        float b1 = xls[s1 * 64 + lane],      c1 = xls[s1 * 64 + 32 + lane];
        float b2 = xls[s2 * 64 + lane],      c2 = xls[s2 * 64 + 32 + lane];
        float b3 = xls[s3 * 64 + lane],      c3 = xls[s3 * 64 + 32 + lane];
        a0 += (b0 + b1) + (b2 + b3);
        a1 += (c0 + c1) + (c2 + c3);
    }
    for (; t < end; t++) {
        int s = __ldg(&csr[t]);
        a0 += xls[s * 64 + lane];
        a1 += xls[s * 64 + 32 + lane];
    }
    float dd = dis[w];
    P[(size_t)w * 64 + lane]      += dd * (a0 + xls[w * 64 + lane]);
    P[(size_t)w * 64 + 32 + lane] += dd * (a1 + xls[w * 64 + 32 + lane]);
}

__global__ void k_sage_gather(const int* __restrict__ off, const int* __restrict__ csr,
                              const float* __restrict__ xa, float* __restrict__ SA,
                              int n, int E) {
    int w = (blockIdx.x * blockDim.x + threadIdx.x) >> 5;
    int lane = threadIdx.x & 31;
    if (w >= n) return;
    int beg = off[w], end = (w == n - 1) ? E : off[w + 1];
    float a0 = 0.f, a1 = 0.f;
    int t = beg;
    for (; t + 4 <= end; t += 4) {
        int s0 = __ldg(&csr[t]),     s1 = __ldg(&csr[t + 1]);
        int s2 = __ldg(&csr[t + 2]), s3 = __ldg(&csr[t + 3]);
        float b0 = xa[s0 * 64 + lane],      c0 = xa[s0 * 64 + 32 + lane];
        float b1 = xa[s1 * 64 + lane],      c1 = xa[s1 * 64 + 32 + lane];
        float b2 = xa[s2 * 64 + lane],      c2 = xa[s2 * 64 + 32 + lane];
        float b3 = xa[s3 * 64 + lane],      c3 = xa[s3 * 64 + 32 + lane];
        a0 += (b0 + b1) + (b2 + b3);
        a1 += (c0 + c1) + (c2 + c3);
    }
    for (; t < end; t++) {
        int s = __ldg(&csr[t]);
        a0 += xa[s * 64 + lane];
        a1 += xa[s * 64 + 32 + lane];
    }
    float r = 1.0f / fmaxf((float)(end - beg), 1.0f);
    SA[(size_t)w * 64 + lane]      = a0 * r;
    SA[(size_t)w * 64 + 32 + lane] = a1 * r;
}

// fused GAT: per-author softmax denom + weighted gather + bias + relu
__global__ void k_gat_gather(const int* __restrict__ off, const int* __restrict__ csr,
                             const float* __restrict__ asrc, const float* __restrict__ adst,
                             const float* __restrict__ XS, const float* __restrict__ bias,
                             float* __restrict__ out, int n, int E) {
    int w = (blockIdx.x * blockDim.x + threadIdx.x) >> 5;
    int lane = threadIdx.x & 31;
    if (w >= n) return;
    int beg = off[w], end = (w == n - 1) ? E : off[w + 1];
    float ad = adst[w];
    float den = 0.f, a0 = 0.f, a1 = 0.f;
    int t = beg;
    for (; t + 4 <= end; t += 4) {
        int p0 = __ldg(&csr[t]),     p1 = __ldg(&csr[t + 1]);
        int p2 = __ldg(&csr[t + 2]), p3 = __ldg(&csr[t + 3]);
        float e0 = asrc[p0] + ad; e0 = (e0 > 0.f) ? e0 : 0.2f * e0;
        float e1 = asrc[p1] + ad; e1 = (e1 > 0.f) ? e1 : 0.2f * e1;
        float e2 = asrc[p2] + ad; e2 = (e2 > 0.f) ? e2 : 0.2f * e2;
        float e3 = asrc[p3] + ad; e3 = (e3 > 0.f) ? e3 : 0.2f * e3;
        float x0 = __expf(e0), x1 = __expf(e1), x2 = __expf(e2), x3 = __expf(e3);
        float b0 = XS[p0 * 64 + lane],      c0 = XS[p0 * 64 + 32 + lane];
        float b1 = XS[p1 * 64 + lane],      c1 = XS[p1 * 64 + 32 + lane];
        float b2 = XS[p2 * 64 + lane],      c2 = XS[p2 * 64 + 32 + lane];
        float b3 = XS[p3 * 64 + lane],      c3 = XS[p3 * 64 + 32 + lane];
        den += (x0 + x1) + (x2 + x3);
        a0 += (x0 * b0 + x1 * b1) + (x2 * b2 + x3 * b3);
        a1 += (x0 * c0 + x1 * c1) + (x2 * c2 + x3 * c3);
    }
    for (; t < end; t++) {
        int p = __ldg(&csr[t]);
        float e = asrc[p] + ad; e = (e > 0.f) ? e : 0.2f * e;
        float x = __expf(e);
        den += x;
        a0 += x * XS[p * 64 + lane];
        a1 += x * XS[p * 64 + 32 + lane];
    }
    float r = (den > 0.f) ? (1.0f / den) : 0.f;
    float o0 = a0 * r + bias[lane];
    float o1 = a1 * r + bias[lane + 32];
    out[(size_t)w * 64 + lane]      = fmaxf(o0, 0.f);
    out[(size_t)w * 64 + 32 + lane] = fmaxf(o1, 0.f);
}

// ---------------- f32x2 register-blocked GEMM, compile-time epilogue ----------------
// Round-3 proven mainloop: 256 thr, tile M=128, thread = 4 rows x (N/8) cols.
// MODE: 0 = plain (Y = X@W)
//       1 = rowscale (Y = (X@W) * rs[row])
//       2 = combine  (Y = relu(X@W + addsrc + b0[col] + b1[col]))
//       3 = dot      (Y = X@W; dotout[row] = dot(Y[row,:], av))
//       4 = bias     (Y = X@W + b0[col])
#define M_PLAIN 0
#define M_SCALE 1
#define M_COMB  2
#define M_DOT   3
#define M_BIAS  4
template <int K, int N, int MODE>
__global__ void __launch_bounds__(256) k_gemm2(
        const float* __restrict__ X, const float* __restrict__ W,
        const float* __restrict__ b0, const float* __restrict__ b1,
        const float* __restrict__ addsrc, const float* __restrict__ rs,
        const float* __restrict__ av, float* __restrict__ dotout,
        float* __restrict__ Y, int M) {
    constexpr int CPT = N / 8;
    constexpr int QP  = CPT / 2;
    __shared__ __align__(16) float  Wc[32 * N];
    __shared__ __align__(16) float2 Xd[128 * 33];
    int tid = threadIdx.x;
    int tx = tid & 7, ty = tid >> 3;
    int base = blockIdx.x * 128;

    unsigned long long accv[4][QP];
    #pragma unroll
    for (int i = 0; i < 4; i++)
        #pragma unroll
        for (int q = 0; q < QP; q++) accv[i][q] = 0ull;

    for (int kc = 0; kc < K; kc += 32) {
        __syncthreads();
        #pragma unroll
        for (int it = 0; it < (32 * N) / 256; it++) {
            int t = tid + it * 256;
            Wc[t] = W[kc * N + t];
        }
        #pragma unroll
        for (int it = 0; it < 16; it++) {
            int idx = tid + it * 256;
            int r = idx >> 5, k = idx & 31;
            int rr = base + r;
            float v = (rr < M) ? X[(size_t)rr * K + kc + k] : 0.f;
            Xd[r * 33 + k] = make_float2(v, v);
        }
        __syncthreads();
        #pragma unroll
        for (int k = 0; k < 32; k++) {
            unsigned long long a[4];
            #pragma unroll
            for (int i = 0; i < 4; i++)
                a[i] = *(const unsigned long long*)&Xd[(ty * 4 + i) * 33 + k];
            #pragma unroll
            for (int h = 0; h < QP / 2; h++) {
                ulonglong2 wp = *(const ulonglong2*)&Wc[k * N + tx * CPT + h * 4];
                #pragma unroll
                for (int i = 0; i < 4; i++) {
                    asm("fma.rn.f32x2 %0, %1, %2, %0;"
                        : "+l"(accv[i][2 * h]) : "l"(a[i]), "l"(wp.x));
                    asm("fma.rn.f32x2 %0, %1, %2, %0;"
                        : "+l"(accv[i][2 * h + 1]) : "l"(a[i]), "l"(wp.y));
                }
            }
        }
    }
    #pragma unroll
    for (int i = 0; i < 4; i++) {
        int row = base + ty * 4 + i;
        if (row >= M) continue;
        float scale = 1.f;
        if (MODE == M_SCALE) scale = rs[row];
        float d = 0.f;
        #pragma unroll
        for (int q = 0; q < QP; q++) {
            float2 v = *(float2*)&accv[i][q];
            int col = tx * CPT + 2 * q;
            if (MODE == M_SCALE) { v.x *= scale; v.y *= scale; }
            if (MODE == M_BIAS) {
                float2 b = *(const float2*)&b0[col];
                v.x += b.x; v.y += b.y;
            }
            if (MODE == M_COMB) {
                float2 a2 = *(const float2*)&addsrc[(size_t)row * N + col];
                float2 ba = *(const float2*)&b0[col];
                float2 bb = *(const float2*)&b1[col];
                v.x = fmaxf(v.x + a2.x + ba.x + bb.x, 0.f);
                v.y = fmaxf(v.y + a2.y + ba.y + bb.y, 0.f);
            }
            *(float2*)&Y[(size_t)row * N + col] = v;
            if (MODE == M_DOT) {
                float2 w2 = *(const float2*)&av[col];
                d += v.x * w2.x + v.y * w2.y;
            }
        }
        if (MODE == M_DOT) {
            #pragma unroll
            for (int o = 1; o < 8; o <<= 1) d += __shfl_xor_sync(0xFFFFFFFFu, d, o);
            if (tx == 0) dotout[row] = d;
        }
    }
}

// ---------------- host ----------------
static inline int cdiv(long long a, int b) { return (int)((a + b - 1) / b); }

extern "C" void kernel_launch(void* const* d_in, const int* in_sizes, int n_in,
                              void* d_out, int out_size) {
    const float* xp       = (const float*)d_in[0];
    const float* xa       = (const float*)d_in[1];
    const float* gcn_W0   = (const float*)d_in[2];
    const float* gcn_b0   = (const float*)d_in[3];
    const float* sage_Wl0 = (const float*)d_in[4];
    const float* sage_bl0 = (const float*)d_in[5];
    const float* sage_Wr0 = (const float*)d_in[6];
    const float* gat_Ws0  = (const float*)d_in[7];
    const float* gat_Wd0  = (const float*)d_in[8];
    const float* gat_as0  = (const float*)d_in[9];
    const float* gat_ad0  = (const float*)d_in[10];
    const float* gat_b0   = (const float*)d_in[11];
    const float* gat_Ws1  = (const float*)d_in[17];
    const float* gat_Wd1  = (const float*)d_in[18];
    const float* gat_as1  = (const float*)d_in[19];
    const float* gat_ad1  = (const float*)d_in[20];
    const float* gat_b1   = (const float*)d_in[21];
    const float* lin_W    = (const float*)d_in[22];
    const float* lin_b    = (const float*)d_in[23];
    const int* cs = (const int*)d_in[24];
    const int* cd = (const int*)d_in[25];
    const int* ws = (const int*)d_in[26];  // author idx of writes edge
    const int* wd = (const int*)d_in[27];  // paper idx of writes edge
    float* out = (float*)d_out;

    void* p;
    #define SYM(name) cudaGetSymbolAddress(&p, g_##name)
    SYM(xls);  float* xls = (float*)p;
    SYM(P);    float* P   = (float*)p;
    SYM(SA);   float* SA  = (float*)p;
    SYM(XS);   float* XS  = (float*)p;
    SYM(XD);   float* XD  = (float*)p;
    SYM(xp1);  float* xp1 = (float*)p;
    SYM(xa1);  float* xa1 = (float*)p;
    SYM(dis);  float* dis = (float*)p;
    SYM(asrc); float* asrc = (float*)p;
    SYM(adst); float* adst = (float*)p;
    SYM(degC); int* degC = (int*)p;
    SYM(degWp); int* degWp = (int*)p;
    SYM(degWa); int* degWa = (int*)p;
    SYM(offC); int* offC = (int*)p;
    SYM(offWp); int* offWp = (int*)p;
    SYM(offWa); int* offWa = (int*)p;
    SYM(curC); int* curC = (int*)p;
    SYM(curWp); int* curWp = (int*)p;
    SYM(curWa); int* curWa = (int*)p;
    SYM(bsum); int* bsum = (int*)p;
    SYM(csrC); int* csrC = (int*)p;
    SYM(csrWp); int* csrWp = (int*)p;
    SYM(csrWa); int* csrWa = (int*)p;
    #undef SYM

    const int T = 256;
    #define GEMM(Kk, Nn, MODE, Xs, Ws_, B0, B1, ADD, RS, AV, DOT, Yy, Mm) \
        k_gemm2<Kk, Nn, MODE><<<cdiv(Mm, 128), 256>>>(Xs, Ws_, B0, B1, ADD, RS, AV, DOT, Yy, Mm)

    // ---- CSR build: cites-by-dst(paper), writes-by-paper, writes-by-author ----
    k_zero_i<<<cdiv(NP, T), T>>>(degC, NP);
    k_zero_i<<<cdiv(NP, T), T>>>(degWp, NP);
    k_zero_i<<<cdiv(NA, T), T>>>(degWa, NA);
    k_count<<<cdiv(EC, T), T>>>(cd, degC, EC);
    k_count<<<cdiv(EW, T), T>>>(wd, degWp, EW);
    k_count<<<cdiv(EW, T), T>>>(ws, degWa, EW);
    k_dis<<<cdiv(NP, T), T>>>(degC, dis, NP);

    k_scan1<<<cdiv(NP, 512), 512>>>(degC, offC, bsum, NP);
    k_scan2<<<1, 512>>>(bsum, cdiv(NP, 512));
    k_scan3<<<cdiv(NP, T), T>>>(offC, curC, bsum, NP);
    k_fill<<<cdiv(EC, T), T>>>(cd, cs, curC, csrC, EC);

    k_scan1<<<cdiv(NP, 512), 512>>>(degWp, offWp, bsum, NP);
    k_scan2<<<1, 512>>>(bsum, cdiv(NP, 512));
    k_scan3<<<cdiv(NP, T), T>>>(offWp, curWp, bsum, NP);
    k_fill<<<cdiv(EW, T), T>>>(wd, ws, curWp, csrWp, EW);

    k_scan1<<<cdiv(NA, 512), 512>>>(degWa, offWa, bsum, NA);
    k_scan2<<<1, 512>>>(bsum, cdiv(NA, 512));
    k_scan3<<<cdiv(NA, T), T>>>(offWa, curWa, bsum, NA);
    k_fill<<<cdiv(EW, T), T>>>(ws, wd, curWa, csrWa, EW);

    // ---- layer 0: GCN (paper<-paper) + SAGE root term ----
    GEMM(128, 64, M_SCALE, xp, gcn_W0, nullptr, nullptr, nullptr, dis, nullptr, nullptr, xls, NP);
    GEMM(128, 64, M_PLAIN, xp, sage_Wr0, nullptr, nullptr, nullptr, nullptr, nullptr, nullptr, P, NP);
    k_gcn_gather<<<cdiv((long long)NP * 32, T), T>>>(offC, csrC, xls, dis, P, NP, EC);

    // ---- layer 0: SAGE gather + fused combine: xp1 = relu(SA@Wl + P + b0 + b1) ----
    k_sage_gather<<<cdiv((long long)NP * 32, T), T>>>(offWp, csrWp, xa, SA, NP, EW);
    GEMM(64, 64, M_COMB, SA, sage_Wl0, gcn_b0, sage_bl0, P, nullptr, nullptr, nullptr, xp1, NP);

    // ---- layer 0: GAT (author<-paper), rowdots fused into GEMM epilogues ----
    GEMM(128, 64, M_DOT, xp, gat_Ws0, nullptr, nullptr, nullptr, nullptr, gat_as0, asrc, XS, NP);
    GEMM(64, 64, M_DOT, xa, gat_Wd0, nullptr, nullptr, nullptr, nullptr, gat_ad0, adst, XD, NA);
    k_gat_gather<<<cdiv((long long)NA * 32, T), T>>>(offWa, csrWa, asrc, adst, XS,
                                                     gat_b0, xa1, NA, EW);

    // ---- layer 1: only GAT is live (paper update is dead code) ----
    GEMM(64, 64, M_DOT, xp1, gat_Ws1, nullptr, nullptr, nullptr, nullptr, gat_as1, asrc, XS, NP);
    GEMM(64, 64, M_DOT, xa1, gat_Wd1, nullptr, nullptr, nullptr, nullptr, gat_ad1, adst, XD, NA);
    k_gat_gather<<<cdiv((long long)NA * 32, T), T>>>(offWa, csrWa, asrc, adst, XS,
                                                     gat_b1, xa1, NA, EW);

    // ---- output head ----
    GEMM(64, 32, M_BIAS, xa1, lin_W, lin_b, nullptr, nullptr, nullptr, nullptr, nullptr, out, NA);
    #undef GEMM
}

// round 7
// speedup vs baseline: 1.1991x; 1.1195x over previous
#include <cuda_runtime.h>
#include <cstdint>
#include <cstddef>

#define NP 200000
#define NA 100000
#define EC 4000000
#define EW 2000000

// ---------------- device scratch (allocation-free) ----------------
__device__ float g_xls[(size_t)NP * 64];   // raw x_paper @ gcn_W
__device__ float g_P  [(size_t)NP * 64];   // paper accumulation
__device__ float g_SA [(size_t)NP * 64];   // sage neighbor mean
__device__ float g_XS [(size_t)NP * 64];   // gat L0 source feats (paper)
__device__ float g_XS1[(size_t)NP * 64];   // gat L1 source feats (paper)
__device__ float g_XD [(size_t)NA * 64];   // gat dst feats (author)
__device__ float g_xp1[(size_t)NP * 64];   // x_paper after layer 0
__device__ float g_xa1[(size_t)NA * 64];   // x_author after layer 0/1
__device__ float g_dis [NP];
__device__ float g_asrc[NP],  g_adst[NA];
__device__ float g_asrc1[NP], g_adst1[NA];
__device__ int g_degC[NP], g_degWp[NP], g_degWa[NA];
__device__ int g_offC[NP], g_offWp[NP], g_offWa[NA];
__device__ int g_curC[NP], g_curWp[NP], g_curWa[NA];
__device__ int g_bsumA[512], g_bsumB[512];
__device__ int g_csrC[EC], g_csrWp[EW], g_csrWa[EW];

// ---------------- utility kernels ----------------
__global__ void k_zero_i(int* p, int n) {
    int i = blockIdx.x * blockDim.x + threadIdx.x;
    if (i < n) p[i] = 0;
}
__global__ void k_count(const int* __restrict__ idx, int* cnt, int E) {
    int i = blockIdx.x * blockDim.x + threadIdx.x;
    if (i < E) atomicAdd(&cnt[idx[i]], 1);
}
__global__ void k_dis(const int* __restrict__ cnt, float* dis, int n) {
    int i = blockIdx.x * blockDim.x + threadIdx.x;
    if (i < n) dis[i] = rsqrtf((float)cnt[i] + 1.0f);
}

// ---------------- scan (3-phase, blocks of 512) ----------------
__global__ void k_scan1(const int* __restrict__ deg, int* off, int* bsum, int n) {
    __shared__ int sh[512];
    int t = threadIdx.x, i = blockIdx.x * 512 + t;
    int v = (i < n) ? deg[i] : 0;
    sh[t] = v; __syncthreads();
    #pragma unroll
    for (int o = 1; o < 512; o <<= 1) {
        int x = (t >= o) ? sh[t - o] : 0;
        __syncthreads(); sh[t] += x; __syncthreads();
    }
    if (i < n) off[i] = sh[t] - v;
    if (t == 511) bsum[blockIdx.x] = sh[511];
}
__global__ void k_scan2(int* bsum, int nb) {
    __shared__ int sh[512];
    int t = threadIdx.x;
    int v = (t < nb) ? bsum[t] : 0;
    sh[t] = v; __syncthreads();
    #pragma unroll
    for (int o = 1; o < 512; o <<= 1) {
        int x = (t >= o) ? sh[t - o] : 0;
        __syncthreads(); sh[t] += x; __syncthreads();
    }
    if (t < nb) bsum[t] = sh[t] - v;
}
__global__ void k_scan3(int* off, int* cur, const int* __restrict__ bsum, int n) {
    int i = blockIdx.x * blockDim.x + threadIdx.x;
    if (i < n) { int v = off[i] + bsum[i >> 9]; off[i] = v; cur[i] = v; }
}
__global__ void k_fill(const int* __restrict__ dst, const int* __restrict__ src,
                       int* cur, int* csr, int E) {
    int i = blockIdx.x * blockDim.x + threadIdx.x;
    if (i < E) {
        int pos = atomicAdd(&cur[dst[i]], 1);
        csr[pos] = src[i];
    }
}

// ---------------- gathers (1 warp / node, 2 cols / lane) ----------------
// P += dis[w] * (sum_{nbr} dis[s]*xls[s] + dis[w]*xls[w])   (P pre-holds sage_Wr part)
__global__ void k_gcn_gather(const int* __restrict__ off, const int* __restrict__ csr,
                             const float* __restrict__ xls, const float* __restrict__ dis,
                             float* __restrict__ P, int n, int E) {
    int w = (blockIdx.x * blockDim.x + threadIdx.x) >> 5;
    int lane = threadIdx.x & 31;
    if (w >= n) return;
    int beg = off[w], end = (w == n - 1) ? E : off[w + 1];
    float a0 = 0.f, a1 = 0.f;
    int t = beg;
    for (; t + 4 <= end; t += 4) {
        int s0 = __ldg(&csr[t]),     s1 = __ldg(&csr[t + 1]);
        int s2 = __ldg(&csr[t + 2]), s3 = __ldg(&csr[t + 3]);
        float d0 = __ldg(&dis[s0]), d1 = __ldg(&dis[s1]);
        float d2 = __ldg(&dis[s2]), d3 = __ldg(&dis[s3]);
        float b0 = xls[s0 * 64 + lane],      c0 = xls[s0 * 64 + 32 + lane];
        float b1 = xls[s1 * 64 + lane],      c1 = xls[s1 * 64 + 32 + lane];
        float b2 = xls[s2 * 64 + lane],      c2 = xls[s2 * 64 + 32 + lane];
        float b3 = xls[s3 * 64 + lane],      c3 = xls[s3 * 64 + 32 + lane];
        a0 += (d0 * b0 + d1 * b1) + (d2 * b2 + d3 * b3);
        a1 += (d0 * c0 + d1 * c1) + (d2 * c2 + d3 * c3);
    }
    for (; t < end; t++) {
        int s = __ldg(&csr[t]);
        float d = __ldg(&dis[s]);
        a0 += d * xls[s * 64 + lane];
        a1 += d * xls[s * 64 + 32 + lane];
    }
    float dd = dis[w];
    P[(size_t)w * 64 + lane]      += dd * (a0 + dd * xls[w * 64 + lane]);
    P[(size_t)w * 64 + 32 + lane] += dd * (a1 + dd * xls[w * 64 + 32 + lane]);
}

__global__ void k_sage_gather(const int* __restrict__ off, const int* __restrict__ csr,
                              const float* __restrict__ xa, float* __restrict__ SA,
                              int n, int E) {
    int w = (blockIdx.x * blockDim.x + threadIdx.x) >> 5;
    int lane = threadIdx.x & 31;
    if (w >= n) return;
    int beg = off[w], end = (w == n - 1) ? E : off[w + 1];
    float a0 = 0.f, a1 = 0.f;
    int t = beg;
    for (; t + 4 <= end; t += 4) {
        int s0 = __ldg(&csr[t]),     s1 = __ldg(&csr[t + 1]);
        int s2 = __ldg(&csr[t + 2]), s3 = __ldg(&csr[t + 3]);
        float b0 = xa[s0 * 64 + lane],      c0 = xa[s0 * 64 + 32 + lane];
        float b1 = xa[s1 * 64 + lane],      c1 = xa[s1 * 64 + 32 + lane];
        float b2 = xa[s2 * 64 + lane],      c2 = xa[s2 * 64 + 32 + lane];
        float b3 = xa[s3 * 64 + lane],      c3 = xa[s3 * 64 + 32 + lane];
        a0 += (b0 + b1) + (b2 + b3);
        a1 += (c0 + c1) + (c2 + c3);
    }
    for (; t < end; t++) {
        int s = __ldg(&csr[t]);
        a0 += xa[s * 64 + lane];
        a1 += xa[s * 64 + 32 + lane];
    }
    float r = 1.0f / fmaxf((float)(end - beg), 1.0f);
    SA[(size_t)w * 64 + lane]      = a0 * r;
    SA[(size_t)w * 64 + 32 + lane] = a1 * r;
}

// fused GAT: per-author softmax denom + weighted gather + bias + relu
__global__ void k_gat_gather(const int* __restrict__ off, const int* __restrict__ csr,
                             const float* __restrict__ asrc, const float* __restrict__ adst,
                             const float* __restrict__ XS, const float* __restrict__ bias,
                             float* __restrict__ out, int n, int E) {
    int w = (blockIdx.x * blockDim.x + threadIdx.x) >> 5;
    int lane = threadIdx.x & 31;
    if (w >= n) return;
    int beg = off[w], end = (w == n - 1) ? E : off[w + 1];
    float ad = adst[w];
    float den = 0.f, a0 = 0.f, a1 = 0.f;
    int t = beg;
    for (; t + 4 <= end; t += 4) {
        int p0 = __ldg(&csr[t]),     p1 = __ldg(&csr[t + 1]);
        int p2 = __ldg(&csr[t + 2]), p3 = __ldg(&csr[t + 3]);
        float e0 = asrc[p0] + ad; e0 = (e0 > 0.f) ? e0 : 0.2f * e0;
        float e1 = asrc[p1] + ad; e1 = (e1 > 0.f) ? e1 : 0.2f * e1;
        float e2 = asrc[p2] + ad; e2 = (e2 > 0.f) ? e2 : 0.2f * e2;
        float e3 = asrc[p3] + ad; e3 = (e3 > 0.f) ? e3 : 0.2f * e3;
        float x0 = __expf(e0), x1 = __expf(e1), x2 = __expf(e2), x3 = __expf(e3);
        float b0 = XS[p0 * 64 + lane],      c0 = XS[p0 * 64 + 32 + lane];
        float b1 = XS[p1 * 64 + lane],      c1 = XS[p1 * 64 + 32 + lane];
        float b2 = XS[p2 * 64 + lane],      c2 = XS[p2 * 64 + 32 + lane];
        float b3 = XS[p3 * 64 + lane],      c3 = XS[p3 * 64 + 32 + lane];
        den += (x0 + x1) + (x2 + x3);
        a0 += (x0 * b0 + x1 * b1) + (x2 * b2 + x3 * b3);
        a1 += (x0 * c0 + x1 * c1) + (x2 * c2 + x3 * c3);
    }
    for (; t < end; t++) {
        int p = __ldg(&csr[t]);
        float e = asrc[p] + ad; e = (e > 0.f) ? e : 0.2f * e;
        float x = __expf(e);
        den += x;
        a0 += x * XS[p * 64 + lane];
        a1 += x * XS[p * 64 + 32 + lane];
    }
    float r = (den > 0.f) ? (1.0f / den) : 0.f;
    float o0 = a0 * r + bias[lane];
    float o1 = a1 * r + bias[lane + 32];
    out[(size_t)w * 64 + lane]      = fmaxf(o0, 0.f);
    out[(size_t)w * 64 + 32 + lane] = fmaxf(o1, 0.f);
}

// ---------------- f32x2 register-blocked GEMM, compile-time epilogue ----------------
#define M_PLAIN 0
#define M_COMB  2
#define M_DOT   3
#define M_BIAS  4
template <int K, int N, int MODE>
__global__ void __launch_bounds__(256) k_gemm2(
        const float* __restrict__ X, const float* __restrict__ W,
        const float* __restrict__ b0, const float* __restrict__ b1,
        const float* __restrict__ addsrc,
        const float* __restrict__ av, float* __restrict__ dotout,
        float* __restrict__ Y, int M) {
    constexpr int CPT = N / 8;
    constexpr int QP  = CPT / 2;
    __shared__ __align__(16) float  Wc[32 * N];
    __shared__ __align__(16) float2 Xd[128 * 33];
    int tid = threadIdx.x;
    int tx = tid & 7, ty = tid >> 3;
    int base = blockIdx.x * 128;

    unsigned long long accv[4][QP];
    #pragma unroll
    for (int i = 0; i < 4; i++)
        #pragma unroll
        for (int q = 0; q < QP; q++) accv[i][q] = 0ull;

    for (int kc = 0; kc < K; kc += 32) {
        __syncthreads();
        #pragma unroll
        for (int it = 0; it < (32 * N) / 256; it++) {
            int t = tid + it * 256;
            Wc[t] = W[kc * N + t];
        }
        #pragma unroll
        for (int it = 0; it < 16; it++) {
            int idx = tid + it * 256;
            int r = idx >> 5, k = idx & 31;
            int rr = base + r;
            float v = (rr < M) ? X[(size_t)rr * K + kc + k] : 0.f;
            Xd[r * 33 + k] = make_float2(v, v);
        }
        __syncthreads();
        #pragma unroll
        for (int k = 0; k < 32; k++) {
            unsigned long long a[4];
            #pragma unroll
            for (int i = 0; i < 4; i++)
                a[i] = *(const unsigned long long*)&Xd[(ty * 4 + i) * 33 + k];
            #pragma unroll
            for (int h = 0; h < QP / 2; h++) {
                ulonglong2 wp = *(const ulonglong2*)&Wc[k * N + tx * CPT + h * 4];
                #pragma unroll
                for (int i = 0; i < 4; i++) {
                    asm("fma.rn.f32x2 %0, %1, %2, %0;"
                        : "+l"(accv[i][2 * h]) : "l"(a[i]), "l"(wp.x));
                    asm("fma.rn.f32x2 %0, %1, %2, %0;"
                        : "+l"(accv[i][2 * h + 1]) : "l"(a[i]), "l"(wp.y));
                }
            }
        }
    }
    #pragma unroll
    for (int i = 0; i < 4; i++) {
        int row = base + ty * 4 + i;
        if (row >= M) continue;
        float d = 0.f;
        #pragma unroll
        for (int q = 0; q < QP; q++) {
            float2 v = *(float2*)&accv[i][q];
            int col = tx * CPT + 2 * q;
            if (MODE == M_BIAS) {
                float2 b = *(const float2*)&b0[col];
                v.x += b.x; v.y += b.y;
            }
            if (MODE == M_COMB) {
                float2 a2 = *(const float2*)&addsrc[(size_t)row * N + col];
                float2 ba = *(const float2*)&b0[col];
                float2 bb = *(const float2*)&b1[col];
                v.x = fmaxf(v.x + a2.x + ba.x + bb.x, 0.f);
                v.y = fmaxf(v.y + a2.y + ba.y + bb.y, 0.f);
            }
            *(float2*)&Y[(size_t)row * N + col] = v;
            if (MODE == M_DOT) {
                float2 w2 = *(const float2*)&av[col];
                d += v.x * w2.x + v.y * w2.y;
            }
        }
        if (MODE == M_DOT) {
            #pragma unroll
            for (int o = 1; o < 8; o <<= 1) d += __shfl_xor_sync(0xFFFFFFFFu, d, o);
            if (tx == 0) dotout[row] = d;
        }
    }
}

// ---------------- host ----------------
static inline int cdiv(long long a, int b) { return (int)((a + b - 1) / b); }

extern "C" void kernel_launch(void* const* d_in, const int* in_sizes, int n_in,
                              void* d_out, int out_size) {
    const float* xp       = (const float*)d_in[0];
    const float* xa       = (const float*)d_in[1];
    const float* gcn_W0   = (const float*)d_in[2];
    const float* gcn_b0   = (const float*)d_in[3];
    const float* sage_Wl0 = (const float*)d_in[4];
    const float* sage_bl0 = (const float*)d_in[5];
    const float* sage_Wr0 = (const float*)d_in[6];
    const float* gat_Ws0  = (const float*)d_in[7];
    const float* gat_Wd0  = (const float*)d_in[8];
    const float* gat_as0  = (const float*)d_in[9];
    const float* gat_ad0  = (const float*)d_in[10];
    const float* gat_b0   = (const float*)d_in[11];
    const float* gat_Ws1  = (const float*)d_in[17];
    const float* gat_Wd1  = (const float*)d_in[18];
    const float* gat_as1  = (const float*)d_in[19];
    const float* gat_ad1  = (const float*)d_in[20];
    const float* gat_b1   = (const float*)d_in[21];
    const float* lin_W    = (const float*)d_in[22];
    const float* lin_b    = (const float*)d_in[23];
    const int* cs = (const int*)d_in[24];
    const int* cd = (const int*)d_in[25];
    const int* ws = (const int*)d_in[26];  // author idx of writes edge
    const int* wd = (const int*)d_in[27];  // paper idx of writes edge
    float* out = (float*)d_out;

    void* p;
    #define SYM(name) cudaGetSymbolAddress(&p, g_##name)
    SYM(xls);   float* xls  = (float*)p;
    SYM(P);     float* P    = (float*)p;
    SYM(SA);    float* SA   = (float*)p;
    SYM(XS);    float* XS   = (float*)p;
    SYM(XS1);   float* XS1  = (float*)p;
    SYM(XD);    float* XD   = (float*)p;
    SYM(xp1);   float* xp1  = (float*)p;
    SYM(xa1);   float* xa1  = (float*)p;
    SYM(dis);   float* dis  = (float*)p;
    SYM(asrc);  float* asrc = (float*)p;
    SYM(adst);  float* adst = (float*)p;
    SYM(asrc1); float* asrc1 = (float*)p;
    SYM(adst1); float* adst1 = (float*)p;
    SYM(degC); int* degC = (int*)p;
    SYM(degWp); int* degWp = (int*)p;
    SYM(degWa); int* degWa = (int*)p;
    SYM(offC); int* offC = (int*)p;
    SYM(offWp); int* offWp = (int*)p;
    SYM(offWa); int* offWa = (int*)p;
    SYM(curC); int* curC = (int*)p;
    SYM(curWp); int* curWp = (int*)p;
    SYM(curWa); int* curWa = (int*)p;
    SYM(bsumA); int* bsumA = (int*)p;
    SYM(bsumB); int* bsumB = (int*)p;
    SYM(csrC); int* csrC = (int*)p;
    SYM(csrWp); int* csrWp = (int*)p;
    SYM(csrWa); int* csrWa = (int*)p;
    #undef SYM

    const int T = 256;
    cudaStream_t s0 = 0, sA, sB;
    cudaStreamCreateWithFlags(&sA, cudaStreamNonBlocking);
    cudaStreamCreateWithFlags(&sB, cudaStreamNonBlocking);
    cudaEvent_t eF, eA, eB, eF2, eB2;
    cudaEventCreateWithFlags(&eF,  cudaEventDisableTiming);
    cudaEventCreateWithFlags(&eA,  cudaEventDisableTiming);
    cudaEventCreateWithFlags(&eB,  cudaEventDisableTiming);
    cudaEventCreateWithFlags(&eF2, cudaEventDisableTiming);
    cudaEventCreateWithFlags(&eB2, cudaEventDisableTiming);

    #define GEMM(Kk, Nn, MODE, STRM, Xs, Ws_, B0, B1, ADD, AV, DOT, Yy, Mm) \
        k_gemm2<Kk, Nn, MODE><<<cdiv(Mm, 128), 256, 0, STRM>>>(Xs, Ws_, B0, B1, ADD, AV, DOT, Yy, Mm)

    // ================= fork 1: CSR builds on sA/sB, GEMMs on s0 =================
    cudaEventRecord(eF, s0);
    cudaStreamWaitEvent(sA, eF, 0);
    cudaStreamWaitEvent(sB, eF, 0);

    // sA: cites CSR (paper<-paper) + dis
    k_zero_i<<<cdiv(NP, T), T, 0, sA>>>(degC, NP);
    k_count<<<cdiv(EC, T), T, 0, sA>>>(cd, degC, EC);
    k_dis<<<cdiv(NP, T), T, 0, sA>>>(degC, dis, NP);
    k_scan1<<<cdiv(NP, 512), 512, 0, sA>>>(degC, offC, bsumA, NP);
    k_scan2<<<1, 512, 0, sA>>>(bsumA, cdiv(NP, 512));
    k_scan3<<<cdiv(NP, T), T, 0, sA>>>(offC, curC, bsumA, NP);
    k_fill<<<cdiv(EC, T), T, 0, sA>>>(cd, cs, curC, csrC, EC);

    // sB: both writes CSRs
    k_zero_i<<<cdiv(NP, T), T, 0, sB>>>(degWp, NP);
    k_count<<<cdiv(EW, T), T, 0, sB>>>(wd, degWp, EW);
    k_scan1<<<cdiv(NP, 512), 512, 0, sB>>>(degWp, offWp, bsumB, NP);
    k_scan2<<<1, 512, 0, sB>>>(bsumB, cdiv(NP, 512));
    k_scan3<<<cdiv(NP, T), T, 0, sB>>>(offWp, curWp, bsumB, NP);
    k_fill<<<cdiv(EW, T), T, 0, sB>>>(wd, ws, curWp, csrWp, EW);
    k_zero_i<<<cdiv(NA, T), T, 0, sB>>>(degWa, NA);
    k_count<<<cdiv(EW, T), T, 0, sB>>>(ws, degWa, EW);
    k_scan1<<<cdiv(NA, 512), 512, 0, sB>>>(degWa, offWa, bsumB, NA);
    k_scan2<<<1, 512, 0, sB>>>(bsumB, cdiv(NA, 512));
    k_scan3<<<cdiv(NA, T), T, 0, sB>>>(offWa, curWa, bsumB, NA);
    k_fill<<<cdiv(EW, T), T, 0, sB>>>(ws, wd, curWa, csrWa, EW);

    // s0: the four layer-0 GEMMs (no CSR dependency)
    GEMM(128, 64, M_PLAIN, s0, xp, gcn_W0, nullptr, nullptr, nullptr, nullptr, nullptr, xls, NP);
    GEMM(128, 64, M_PLAIN, s0, xp, sage_Wr0, nullptr, nullptr, nullptr, nullptr, nullptr, P, NP);
    GEMM(128, 64, M_DOT,   s0, xp, gat_Ws0, nullptr, nullptr, nullptr, gat_as0, asrc, XS, NP);
    GEMM(64, 64, M_DOT,    s0, xa, gat_Wd0, nullptr, nullptr, nullptr, gat_ad0, adst, XD, NA);

    // join
    cudaEventRecord(eA, sA);
    cudaEventRecord(eB, sB);
    cudaStreamWaitEvent(s0, eA, 0);
    cudaStreamWaitEvent(s0, eB, 0);

    // ================= fork 2: author branch on sB, paper branch on s0 =================
    cudaEventRecord(eF2, s0);
    cudaStreamWaitEvent(sB, eF2, 0);

    // sB (author): GAT layer 0 -> xa1, then XD1 GEMM + dot -> adst1
    k_gat_gather<<<cdiv((long long)NA * 32, T), T, 0, sB>>>(offWa, csrWa, asrc, adst, XS,
                                                            gat_b0, xa1, NA, EW);
    GEMM(64, 64, M_DOT, sB, xa1, gat_Wd1, nullptr, nullptr, nullptr, gat_ad1, adst1, XD, NA);

    // s0 (paper): GCN gather, SAGE gather, fused combine -> xp1, then XS1 GEMM + dot -> asrc1
    k_gcn_gather<<<cdiv((long long)NP * 32, T), T, 0, s0>>>(offC, csrC, xls, dis, P, NP, EC);
    k_sage_gather<<<cdiv((long long)NP * 32, T), T, 0, s0>>>(offWp, csrWp, xa, SA, NP, EW);
    GEMM(64, 64, M_COMB, s0, SA, sage_Wl0, gcn_b0, sage_bl0, P, nullptr, nullptr, xp1, NP);
    GEMM(64, 64, M_DOT,  s0, xp1, gat_Ws1, nullptr, nullptr, nullptr, gat_as1, asrc1, XS1, NP);

    // join
    cudaEventRecord(eB2, sB);
    cudaStreamWaitEvent(s0, eB2, 0);

    // ================= layer-1 GAT + head (s0) =================
    k_gat_gather<<<cdiv((long long)NA * 32, T), T, 0, s0>>>(offWa, csrWa, asrc1, adst1, XS1,
                                                            gat_b1, xa1, NA, EW);
    GEMM(64, 32, M_BIAS, s0, xa1, lin_W, lin_b, nullptr, nullptr, nullptr, nullptr, out, NA);
    #undef GEMM

    // destroy only outside capture (capture retains the nodes; destroying a forked
    // stream mid-capture can invalidate it)
    cudaStreamCaptureStatus st = cudaStreamCaptureStatusNone;
    cudaStreamIsCapturing(sA, &st);
    if (st == cudaStreamCaptureStatusNone) {
        cudaEventDestroy(eF);  cudaEventDestroy(eA);  cudaEventDestroy(eB);
        cudaEventDestroy(eF2); cudaEventDestroy(eB2);
        cudaStreamDestroy(sA); cudaStreamDestroy(sB);
    }
}